// round 5
// baseline (speedup 1.0000x reference)
#include <cuda_runtime.h>

#define HH 128
#define WW 128
#define HW 16384
#define NB 2

typedef unsigned long long ull;

// ---------------- f32x2 helpers ----------------------------------------------
__device__ __forceinline__ ull pk2(float lo, float hi) {
    ull r; asm("mov.b64 %0,{%1,%2};" : "=l"(r) : "f"(lo), "f"(hi)); return r;
}
__device__ __forceinline__ void upk2(ull v, float& lo, float& hi) {
    asm("mov.b64 {%0,%1},%2;" : "=f"(lo), "=f"(hi) : "l"(v));
}
__device__ __forceinline__ ull ffma2(ull a, ull b, ull c) {
    ull d; asm("fma.rn.f32x2 %0,%1,%2,%3;" : "=l"(d) : "l"(a), "l"(b), "l"(c));
    return d;
}

// ---------------- scratch ----------------------------------------------------
__device__ float g_xup[NB * 256 * HW];            // upsampled x_high (NCHW)
__device__ float g_xmerge[NB * HW * 256];         // concat features, NHWC
__device__ float g_offset[NB * 18 * HW];
__device__ float g_mask[NB * 9 * HW];
__device__ __align__(16) ull g_wtd[64 * 36 * 128]; // deform w, dup'd: [q][ck][co]

// ---------------- 1) bilinear 2x upsample ------------------------------------
__global__ void upsample_kernel(const float* __restrict__ xh) {
    int idx = blockIdx.x * 256 + threadIdx.x;
    int x = idx & 127;
    int y = (idx >> 7) & 127;
    int bc = idx >> 14;
    float sy = (y + 0.5f) * 0.5f - 0.5f;
    float sx = (x + 0.5f) * 0.5f - 0.5f;
    float y0f = floorf(sy), x0f = floorf(sx);
    float fy = sy - y0f, fx = sx - x0f;
    int y0 = (int)y0f, x0 = (int)x0f;
    int y0c = max(y0, 0), y1c = min(y0 + 1, 63);
    int x0c = max(x0, 0), x1c = min(x0 + 1, 63);
    const float* p = xh + (size_t)bc * 4096;
    float v00 = p[y0c * 64 + x0c], v01 = p[y0c * 64 + x1c];
    float v10 = p[y1c * 64 + x0c], v11 = p[y1c * 64 + x1c];
    g_xup[idx] = (1.f - fy) * ((1.f - fx) * v00 + fx * v01)
               + fy * ((1.f - fx) * v10 + fx * v11);
}

// ---------------- 1b) deform weights, duplicated: g_wtd[q][ck][co] -----------
__global__ void wt_kernel(const float* __restrict__ wconv) {
    int idx = blockIdx.x * 256 + threadIdx.x;    // 64*36*128 = 294912
    int co = idx & 127;
    int rest = idx >> 7;
    int ck = rest % 36, q = rest / 36;
    float w = wconv[(size_t)co * 2304 + q * 36 + ck];
    g_wtd[idx] = pk2(w, w);
}

// ---------------- 2) conv3x3 (SAME) + BN + ReLU -> g_xmerge NHWC -------------
// 16x16 threads; tile 32x32 px x 16 co. f32x2 lanes = co pairs (j, j+8).
// ci chunked by 4, DOUBLE-BUFFERED: prefetch chunk c+1 into registers while
// computing chunk c; one barrier per chunk.
// Dynamic smem (78592 B):
//   patch[2][4*1156] ull  (dup'd pixels)   [0, 73984)
//   wpk  [2][288]    ull  (co-pair weights)[73984, 78592)
#define CONV_SMEM_BYTES 78592
template <int CIN>
__global__ void __launch_bounds__(256, 2) conv3x3_bn_relu(
    const float* __restrict__ x, const float* __restrict__ w,
    const float* __restrict__ gg, const float* __restrict__ bbp,
    const float* __restrict__ mmp, const float* __restrict__ vvp,
    int chan_base)
{
    extern __shared__ __align__(16) ull dynsm[];
    ull* patchB[2] = { dynsm, dynsm + 4624 };
    ull* wpkB[2]   = { dynsm + 9248, dynsm + 9248 + 288 };

    int bz = blockIdx.z;
    int b   = bz >> 3;
    int co0 = (bz & 7) << 4;
    int x0 = blockIdx.x << 5, y0 = blockIdx.y << 5;
    int tx = threadIdx.x, ty = threadIdx.y;
    int tid = ty * 16 + tx;

    const float* xb = x + (size_t)b * CIN * HW;

    float pf[19];         // patch prefetch regs
    ull wf0, wf1;         // weight prefetch regs

    // ---- prefetch helpers (inlined by macro-like lambdas) ----
    auto fill_regs = [&](int ci0) {
#pragma unroll
        for (int j = 0; j < 19; j++) {
            int i = tid + j * 256;
            if (j < 18 || tid < 16) {
                int cc = i / 1156, r = i - cc * 1156;
                int py = r / 34, px = r - py * 34;
                int gy = y0 + py - 1, gx = x0 + px - 1;
                float v = 0.f;
                if (gy >= 0 && gy < HH && gx >= 0 && gx < WW)
                    v = __ldg(xb + (size_t)(ci0 + cc) * HW + gy * WW + gx);
                pf[j] = v;
            }
        }
        {
            int i = tid;
            int cc = i / 72, rem = i - cc * 72;
            int k = rem >> 3, j = rem & 7;
            float w0 = __ldg(w + ((size_t)(co0 + j) * CIN + ci0 + cc) * 9 + k);
            float w1 = __ldg(w + ((size_t)(co0 + j + 8) * CIN + ci0 + cc) * 9 + k);
            wf0 = pk2(w0, w1);
        }
        if (tid < 32) {
            int i = tid + 256;
            int cc = i / 72, rem = i - cc * 72;
            int k = rem >> 3, j = rem & 7;
            float w0 = __ldg(w + ((size_t)(co0 + j) * CIN + ci0 + cc) * 9 + k);
            float w1 = __ldg(w + ((size_t)(co0 + j + 8) * CIN + ci0 + cc) * 9 + k);
            wf1 = pk2(w0, w1);
        }
    };
    auto store_regs = [&](int buf) {
        ull* pd = patchB[buf];
        ull* wp = wpkB[buf];
#pragma unroll
        for (int j = 0; j < 19; j++) {
            int i = tid + j * 256;
            if (j < 18 || tid < 16) pd[i] = pk2(pf[j], pf[j]);
        }
        wp[tid] = wf0;
        if (tid < 32) wp[tid + 256] = wf1;
    };

    ull acc2[32];                       // [j][q]
#pragma unroll
    for (int i = 0; i < 32; i++) acc2[i] = 0ull;

    const int NCH = CIN / 4;
    fill_regs(0);
    store_regs(0);
    __syncthreads();

    for (int c = 0; c < NCH; c++) {
        if (c + 1 < NCH) fill_regs((c + 1) * 4);   // LDGs fly under compute

        const ull* pd = patchB[c & 1];
        const ull* wp = wpkB[c & 1];
#pragma unroll
        for (int cc = 0; cc < 4; cc++) {
            const ull* pdc = pd + cc * 1156;
#pragma unroll
            for (int k = 0; k < 9; k++) {
                int dy = k / 3, dx = k % 3;
                ull p0 = pdc[(ty + dy) * 34 + tx + dx];
                ull p1 = pdc[(ty + dy) * 34 + tx + 16 + dx];
                ull p2 = pdc[(ty + 16 + dy) * 34 + tx + dx];
                ull p3 = pdc[(ty + 16 + dy) * 34 + tx + 16 + dx];
                const ull* wr = wp + (cc * 9 + k) * 8;
#pragma unroll
                for (int j = 0; j < 8; j++) {
                    ull wv = wr[j];
                    acc2[j * 4 + 0] = ffma2(wv, p0, acc2[j * 4 + 0]);
                    acc2[j * 4 + 1] = ffma2(wv, p1, acc2[j * 4 + 1]);
                    acc2[j * 4 + 2] = ffma2(wv, p2, acc2[j * 4 + 2]);
                    acc2[j * 4 + 3] = ffma2(wv, p3, acc2[j * 4 + 3]);
                }
            }
        }

        if (c + 1 < NCH) store_regs((c + 1) & 1);
        __syncthreads();
    }

    // BN + ReLU epilogue, NHWC stores
    float sc[16], tc[16];
#pragma unroll
    for (int co = 0; co < 16; co++) {
        int c = co0 + co;
        sc[co] = gg[c] * rsqrtf(vvp[c] + 1e-5f);
        tc[co] = bbp[c] - mmp[c] * sc[co];
    }
#pragma unroll
    for (int q = 0; q < 4; q++) {
        int py = y0 + ty + ((q & 2) << 3);
        int px = x0 + tx + ((q & 1) << 4);
        float* dst = g_xmerge + ((size_t)b * HW + py * WW + px) * 256
                   + chan_base + co0;
        float v[16];
#pragma unroll
        for (int j = 0; j < 8; j++) {
            float lo, hi;
            int qq = ((q & 2) ? 2 : 0) + (q & 1);
            upk2(acc2[j * 4 + qq], lo, hi);
            v[j]     = fmaxf(lo * sc[j]     + tc[j],     0.f);
            v[j + 8] = fmaxf(hi * sc[j + 8] + tc[j + 8], 0.f);
        }
#pragma unroll
        for (int c4 = 0; c4 < 4; c4++)
            ((float4*)dst)[c4] =
                make_float4(v[c4*4], v[c4*4+1], v[c4*4+2], v[c4*4+3]);
    }
}

// ---------------- 3) 1x1 convs: offset (18) + mask (9, sigmoid) --------------
__global__ void __launch_bounds__(256) offmask_kernel(
    const float* __restrict__ w_off, const float* __restrict__ b_off,
    const float* __restrict__ w_mask, const float* __restrict__ b_mask)
{
    __shared__ ull wpk[128 * 27];   // [j = c/2][o]
    int tid = threadIdx.x;
    for (int i = tid; i < 128 * 27; i += 256) {
        int j = i / 27, o = i % 27;
        int c = 2 * j;
        float lo = (o < 18) ? w_off[o * 256 + c]     : w_mask[(o - 18) * 256 + c];
        float hi = (o < 18) ? w_off[o * 256 + c + 1] : w_mask[(o - 18) * 256 + c + 1];
        wpk[i] = pk2(lo, hi);
    }
    __syncthreads();

    int gpix = blockIdx.x * 256 + tid;
    int b = gpix >> 14, pix = gpix & 16383;
    const ull* xp = (const ull*)(g_xmerge + (size_t)gpix * 256);

    ull acc2[27];
#pragma unroll
    for (int o = 0; o < 27; o++) acc2[o] = 0ull;

#pragma unroll 4
    for (int j = 0; j < 128; j++) {
        ull xv = __ldg(xp + j);
#pragma unroll
        for (int o = 0; o < 27; o++)
            acc2[o] = ffma2(wpk[j * 27 + o], xv, acc2[o]);
    }

#pragma unroll
    for (int o = 0; o < 18; o++) {
        float lo, hi; upk2(acc2[o], lo, hi);
        g_offset[((size_t)b * 18 + o) * HW + pix] = lo + hi + b_off[o];
    }
#pragma unroll
    for (int o = 0; o < 9; o++) {
        float lo, hi; upk2(acc2[18 + o], lo, hi);
        float a = lo + hi + b_mask[o];
        g_mask[((size_t)b * 9 + o) * HW + pix] = 1.f / (1.f + __expf(-a));
    }
}

// ---------------- 4) deformable conv 3x3 + ReLU ------------------------------
// block: 8x8 px tile x ALL 128 co; thread = 4 px x 8 co.
// Dynamic smem layout (64512 B total):
//   [0,      36864)  ull   wsk[36*128]   dup'd weights [ck][co]
//   [36864,  46080)  float vals[36*64]   [ck][p]
//   [46080,  55296)  int   mI[4][576]
//   [55296,  64512)  float mW[4][576]
#define DEF_SMEM_BYTES 64512
__global__ void __launch_bounds__(256) deform_kernel(float* __restrict__ out)
{
    extern __shared__ __align__(16) char dyn[];
    ull*   wsk  = (ull*)dyn;
    float* vals = (float*)(dyn + 36864);
    int*   mI0  = (int*)(dyn + 46080);
    int*   mI1  = mI0 + 576;
    int*   mI2  = mI1 + 576;
    int*   mI3  = mI2 + 576;
    float* mW0  = (float*)(dyn + 55296);
    float* mW1  = mW0 + 576;
    float* mW2  = mW1 + 576;
    float* mW3  = mW2 + 576;

    int b = blockIdx.z;
    int gx0 = blockIdx.x << 3, gy0 = blockIdx.y << 3;
    int tid = threadIdx.x;

    for (int e = tid; e < 576; e += 256) {
        int p = e & 63, k = e >> 6;
        int gy = gy0 + (p >> 3), gx = gx0 + (p & 7);
        int pix = gy * WW + gx;
        float dy = g_offset[((size_t)b * 18 + 2 * k) * HW + pix];
        float dx = g_offset[((size_t)b * 18 + 2 * k + 1) * HW + pix];
        float mk = g_mask[((size_t)b * 9 + k) * HW + pix];
        float ys = (float)gy + (float)(k / 3 - 1) + dy;
        float xs = (float)gx + (float)(k % 3 - 1) + dx;
        float y0f = floorf(ys), x0f = floorf(xs);
        int y0 = (int)y0f, x0 = (int)x0f;
        float wy = ys - y0f, wx = xs - x0f;
        bool vy0 = (y0 >= 0) && (y0 < HH);
        bool vy1 = (y0 + 1 >= 0) && (y0 + 1 < HH);
        bool vx0 = (x0 >= 0) && (x0 < WW);
        bool vx1 = (x0 + 1 >= 0) && (x0 + 1 < WW);
        int y0c = min(max(y0, 0), HH - 1), y1c = min(max(y0 + 1, 0), HH - 1);
        int x0c = min(max(x0, 0), WW - 1), x1c = min(max(x0 + 1, 0), WW - 1);
        mI0[e] = (y0c * WW + x0c) * 256;  mW0[e] = (vy0 && vx0) ? (1.f - wy) * (1.f - wx) * mk : 0.f;
        mI1[e] = (y0c * WW + x1c) * 256;  mW1[e] = (vy0 && vx1) ? (1.f - wy) * wx * mk : 0.f;
        mI2[e] = (y1c * WW + x0c) * 256;  mW2[e] = (vy1 && vx0) ? wy * (1.f - wx) * mk : 0.f;
        mI3[e] = (y1c * WW + x1c) * 256;  mW3[e] = (vy1 && vx1) ? wy * wx * mk : 0.f;
    }

    ull acc2[16];                 // [j (8 co)][pr (2 px-pairs)]
#pragma unroll
    for (int i = 0; i < 16; i++) acc2[i] = 0ull;

    const float* xb = g_xmerge + (size_t)b * HW * 256;
    int ppg = tid & 15;      // pixel group: px ppg*4 .. ppg*4+3 (2 pairs)
    int cog = tid >> 4;      // co group:    co cog*8 .. cog*8+7

    for (int q = 0; q < 64; q++) {
        int c0 = q * 4;
        __syncthreads();     // previous GEMM done reading vals/wsk
        // gather: 4 channels per corner via float4
        for (int e = tid; e < 576; e += 256) {
            int i0 = mI0[e], i1 = mI1[e], i2 = mI2[e], i3 = mI3[e];
            float w0 = mW0[e], w1 = mW1[e], w2 = mW2[e], w3 = mW3[e];
            float4 v0 = __ldg((const float4*)(xb + i0 + c0));
            float4 v1 = __ldg((const float4*)(xb + i1 + c0));
            float4 v2 = __ldg((const float4*)(xb + i2 + c0));
            float4 v3 = __ldg((const float4*)(xb + i3 + c0));
            int base = (e >> 6) * 64 + (e & 63);   // k*64 + p
            vals[base]        = w0*v0.x + w1*v1.x + w2*v2.x + w3*v3.x;
            vals[base + 576]  = w0*v0.y + w1*v1.y + w2*v2.y + w3*v3.y;
            vals[base + 1152] = w0*v0.z + w1*v1.z + w2*v2.z + w3*v3.z;
            vals[base + 1728] = w0*v0.w + w1*v1.w + w2*v2.w + w3*v3.w;
        }
        // weights: bulk copy (ull2) of this chunk's dup'd weights
        {
            const ulonglong2* src =
                (const ulonglong2*)(g_wtd + (size_t)q * 4608);
            ulonglong2* dst = (ulonglong2*)wsk;
            for (int i = tid; i < 2304; i += 256)
                dst[i] = __ldg(src + i);
        }
        __syncthreads();
        // GEMM
#pragma unroll 6
        for (int ck = 0; ck < 36; ck++) {
            ull v0 = *(const ull*)&vals[ck * 64 + ppg * 4];
            ull v1 = *(const ull*)&vals[ck * 64 + ppg * 4 + 2];
            const ull* wr = wsk + ck * 128 + cog * 8;
#pragma unroll
            for (int j = 0; j < 8; j++) {
                ull wv = wr[j];
                acc2[j * 2 + 0] = ffma2(wv, v0, acc2[j * 2 + 0]);
                acc2[j * 2 + 1] = ffma2(wv, v1, acc2[j * 2 + 1]);
            }
        }
    }

    // epilogue: ReLU + NCHW store (float2: pixel pairs are gx-contiguous)
#pragma unroll
    for (int j = 0; j < 8; j++) {
        int co = cog * 8 + j;
#pragma unroll
        for (int pr = 0; pr < 2; pr++) {
            float a0, a1; upk2(acc2[j * 2 + pr], a0, a1);
            int p = ppg * 4 + pr * 2;
            int gy = gy0 + (p >> 3), gx = gx0 + (p & 7);
            *(float2*)&out[((size_t)b * 128 + co) * HW + gy * WW + gx] =
                make_float2(fmaxf(a0, 0.f), fmaxf(a1, 0.f));
        }
    }
}

// ---------------- launch -----------------------------------------------------
extern "C" void kernel_launch(void* const* d_in, const int* in_sizes, int n_in,
                              void* d_out, int out_size) {
    const float* x_low  = (const float*)d_in[0];
    const float* x_high = (const float*)d_in[1];
    const float* w_low  = (const float*)d_in[2];
    const float* g_low  = (const float*)d_in[3];
    const float* b_low  = (const float*)d_in[4];
    const float* m_low  = (const float*)d_in[5];
    const float* v_low  = (const float*)d_in[6];
    const float* w_high = (const float*)d_in[7];
    const float* g_high = (const float*)d_in[8];
    const float* b_high = (const float*)d_in[9];
    const float* m_high = (const float*)d_in[10];
    const float* v_high = (const float*)d_in[11];
    const float* w_off  = (const float*)d_in[12];
    const float* b_off  = (const float*)d_in[13];
    const float* w_mask = (const float*)d_in[14];
    const float* b_mask = (const float*)d_in[15];
    const float* w_conv = (const float*)d_in[16];
    float* out = (float*)d_out;

    void* xup_ptr = nullptr;
    cudaGetSymbolAddress(&xup_ptr, g_xup);
    // opt-in >48KB dynamic smem (host-side immediate calls; capture-safe)
    cudaFuncSetAttribute(deform_kernel,
                         cudaFuncAttributeMaxDynamicSharedMemorySize,
                         DEF_SMEM_BYTES);
    cudaFuncSetAttribute(conv3x3_bn_relu<128>,
                         cudaFuncAttributeMaxDynamicSharedMemorySize,
                         CONV_SMEM_BYTES);
    cudaFuncSetAttribute(conv3x3_bn_relu<256>,
                         cudaFuncAttributeMaxDynamicSharedMemorySize,
                         CONV_SMEM_BYTES);

    upsample_kernel<<<(NB * 256 * HW) / 256, 256>>>(x_high);
    wt_kernel<<<(64 * 36 * 128) / 256, 256>>>(w_conv);

    dim3 cb(16, 16);
    conv3x3_bn_relu<128><<<dim3(4, 4, 16), cb, CONV_SMEM_BYTES>>>(
        x_low, w_low, g_low, b_low, m_low, v_low, 0);
    conv3x3_bn_relu<256><<<dim3(4, 4, 16), cb, CONV_SMEM_BYTES>>>(
        (const float*)xup_ptr, w_high, g_high, b_high, m_high, v_high, 128);

    offmask_kernel<<<128, 256>>>(w_off, b_off, w_mask, b_mask);

    deform_kernel<<<dim3(16, 16, NB), 256, DEF_SMEM_BYTES>>>(out);
}

// round 8
// speedup vs baseline: 1.3090x; 1.3090x over previous
#include <cuda_runtime.h>

#define HH 128
#define WW 128
#define HW 16384
#define NB 2

// padded plane geometry for cp.async conv loads
#define PADH 130          // rows: gy in [-1, 129)
#define PADW 136          // cols: gx in [-4, 132)
#define PADHW (PADH * PADW)

typedef unsigned long long ull;

// ---------------- f32x2 helpers ----------------------------------------------
__device__ __forceinline__ ull pk2(float lo, float hi) {
    ull r; asm("mov.b64 %0,{%1,%2};" : "=l"(r) : "f"(lo), "f"(hi)); return r;
}
__device__ __forceinline__ void upk2(ull v, float& lo, float& hi) {
    asm("mov.b64 {%0,%1},%2;" : "=f"(lo), "=f"(hi) : "l"(v));
}
__device__ __forceinline__ ull ffma2(ull a, ull b, ull c) {
    ull d; asm("fma.rn.f32x2 %0,%1,%2,%3;" : "=l"(d) : "l"(a), "l"(b), "l"(c));
    return d;
}
__device__ __forceinline__ unsigned smem_u32(const void* p) {
    unsigned a;
    asm("{ .reg .u64 t; cvta.to.shared.u64 t, %1; cvt.u32.u64 %0, t; }"
        : "=r"(a) : "l"(p));
    return a;
}
__device__ __forceinline__ void cp16(unsigned dst, const void* src) {
    asm volatile("cp.async.ca.shared.global [%0],[%1],16;"
                 :: "r"(dst), "l"(src));
}
#define CP_COMMIT() asm volatile("cp.async.commit_group;")
#define CP_WAIT0()  asm volatile("cp.async.wait_group 0;")
#define CP_WAIT1()  asm volatile("cp.async.wait_group 1;")

// ---------------- scratch ----------------------------------------------------
__device__ __align__(16) float g_xlow_pad[NB * 128 * PADHW];
__device__ __align__(16) float g_xup_pad [NB * 256 * PADHW];
__device__ float g_xmerge[NB * HW * 256];         // concat features, NHWC
__device__ float g_offset[NB * 18 * HW];
__device__ float g_mask[NB * 9 * HW];
__device__ __align__(16) ull g_wtd[64 * 36 * 128];   // deform w dup'd [q][ck][co]
__device__ __align__(16) ull g_wplow [8 * 32 * 288]; // conv-low  co-pair packs
__device__ __align__(16) ull g_wphigh[8 * 64 * 288]; // conv-high co-pair packs

// ---------------- 1a) pad x_low into bordered plane --------------------------
__global__ void pad_low_kernel(const float* __restrict__ x) {
    int idx = blockIdx.x * 256 + threadIdx.x;     // NB*128*PADHW
    int cp = idx % PADW;
    int rp = (idx / PADW) % PADH;
    int bc = idx / PADHW;
    int gx = cp - 4, gy = rp - 1;
    float v = 0.f;
    if (gx >= 0 && gx < WW && gy >= 0 && gy < HH)
        v = x[(size_t)bc * HW + gy * WW + gx];
    g_xlow_pad[idx] = v;
}

// ---------------- 1b) bilinear 2x upsample, written padded -------------------
__global__ void upsample_pad_kernel(const float* __restrict__ xh) {
    int idx = blockIdx.x * 256 + threadIdx.x;     // NB*256*PADHW
    int cp = idx % PADW;
    int rp = (idx / PADW) % PADH;
    int bc = idx / PADHW;
    int gx = cp - 4, gy = rp - 1;
    float v = 0.f;
    if (gx >= 0 && gx < WW && gy >= 0 && gy < HH) {
        float sy = (gy + 0.5f) * 0.5f - 0.5f;
        float sx = (gx + 0.5f) * 0.5f - 0.5f;
        float y0f = floorf(sy), x0f = floorf(sx);
        float fy = sy - y0f, fx = sx - x0f;
        int y0 = (int)y0f, x0 = (int)x0f;
        int y0c = max(y0, 0), y1c = min(y0 + 1, 63);
        int x0c = max(x0, 0), x1c = min(x0 + 1, 63);
        const float* p = xh + (size_t)bc * 4096;
        float v00 = p[y0c * 64 + x0c], v01 = p[y0c * 64 + x1c];
        float v10 = p[y1c * 64 + x0c], v11 = p[y1c * 64 + x1c];
        v = (1.f - fy) * ((1.f - fx) * v00 + fx * v01)
          + fy * ((1.f - fx) * v10 + fx * v11);
    }
    g_xup_pad[idx] = v;
}

// ---------------- 1c) deform weights, duplicated -----------------------------
__global__ void wt_kernel(const float* __restrict__ wconv) {
    int idx = blockIdx.x * 256 + threadIdx.x;    // 64*36*128
    int co = idx & 127;
    int rest = idx >> 7;
    int ck = rest % 36, q = rest / 36;
    float w = wconv[(size_t)co * 2304 + q * 36 + ck];
    g_wtd[idx] = pk2(w, w);
}

// ---------------- 1d) conv weights -> co-pair packs --------------------------
// dst[(cg*NCH + chunk)*288 + cc*72 + k*8 + j] = (w[cg*16+j], w[cg*16+j+8])
__global__ void wpack_kernel(const float* __restrict__ w, ull* __restrict__ dst,
                             int CIN) {
    int t = blockIdx.x * 256 + threadIdx.x;      // 8*(CIN/4)*288
    int e = t % 288;
    int rest = t / 288;
    int NCH = CIN / 4;
    int chunk = rest % NCH, cg = rest / NCH;
    int cc = e / 72, rem = e % 72;
    int k = rem >> 3, j = rem & 7;
    int ci = chunk * 4 + cc;
    float w0 = w[((size_t)(cg * 16 + j) * CIN + ci) * 9 + k];
    float w1 = w[((size_t)(cg * 16 + j + 8) * CIN + ci) * 9 + k];
    dst[t] = pk2(w0, w1);
}

// ---------------- 2) fused conv3x3 + BN + ReLU -> g_xmerge NHWC --------------
// 16x16 threads; tile 32x32 px x 16 co; f32x2 lanes = co pairs (j, j+8).
// ci chunked by 4, TRIPLE-BUFFERED via cp.async (no register cost).
// smem/buffer: patch 4x34x40 floats (21760B) + weights 288 ull (2304B).
#define PATCH_F   (4 * 34 * 40)        // 5440 floats
#define PATCH_B   (PATCH_F * 4)        // 21760 bytes
#define WBUF_B    (288 * 8)            // 2304 bytes
#define CONV_SMEM_BYTES (3 * (PATCH_B + WBUF_B))   // 72192
__global__ void __launch_bounds__(256, 2) conv_fused(
    const float* __restrict__ g_lo, const float* __restrict__ bb_lo,
    const float* __restrict__ mm_lo, const float* __restrict__ vv_lo,
    const float* __restrict__ g_hi, const float* __restrict__ bb_hi,
    const float* __restrict__ mm_hi, const float* __restrict__ vv_hi)
{
    extern __shared__ __align__(16) char dynsm[];
    float* patchS = (float*)dynsm;                 // [3][5440]
    ull*   wS     = (ull*)(dynsm + 3 * PATCH_B);   // [3][288]

    int bz = blockIdx.z;
    bool hi = bz >= 16;
    int bzl = hi ? bz - 16 : bz;
    int b   = bzl >> 3;
    int cg  = bzl & 7;
    int co0 = cg << 4;
    int x0 = blockIdx.x << 5, y0 = blockIdx.y << 5;
    int tx = threadIdx.x, ty = threadIdx.y;
    int tid = ty * 16 + tx;

    const int NCH = hi ? 64 : 32;
    const float* xp = hi ? g_xup_pad + (size_t)b * 256 * PADHW
                         : g_xlow_pad + (size_t)b * 128 * PADHW;
    const ull* wsrc = (hi ? g_wphigh : g_wplow) + (size_t)cg * NCH * 288;
    const float* gg  = hi ? g_hi  : g_lo;
    const float* bbp = hi ? bb_hi : bb_lo;
    const float* mmp = hi ? mm_hi : mm_lo;
    const float* vvp = hi ? vv_hi : vv_lo;
    int chan_base = hi ? 128 : 0;

    unsigned pS0 = smem_u32(patchS);
    unsigned wS0 = smem_u32(wS);

    auto issue = [&](int c, int buf) {
        const float* src_base = xp + (size_t)(c * 4) * PADHW;
        unsigned pdst = pS0 + buf * PATCH_B;
        // patch: 1360 float4 (4 cc x 34 rows x 10 segs)
        for (int i = tid; i < 1360; i += 256) {
            int cc = i / 340;
            int r  = i - cc * 340;
            int row = r / 10, seg = r - row * 10;
            const float* src = src_base + (size_t)cc * PADHW
                             + (y0 + row) * PADW + x0 + seg * 4;
            cp16(pdst + (cc * 1360 + row * 40 + seg * 4) * 4, src);
        }
        // weights: 144 float4 = 288 ull
        if (tid < 144)
            cp16(wS0 + buf * WBUF_B + tid * 16, wsrc + (size_t)c * 288 + tid * 2);
        CP_COMMIT();
    };

    ull acc2[32];                       // [j][q]
#pragma unroll
    for (int i = 0; i < 32; i++) acc2[i] = 0ull;

    issue(0, 0);
    issue(1, 1);

    for (int c = 0; c < NCH; c++) {
        if (c + 1 < NCH) { CP_WAIT1(); } else { CP_WAIT0(); }
        __syncthreads();
        if (c + 2 < NCH) issue(c + 2, (c + 2) % 3);

        int buf = c % 3;
        const float* pd = patchS + buf * PATCH_F;
        const ull*   wp = wS + buf * 288;
#pragma unroll
        for (int cc = 0; cc < 4; cc++) {
            const float* pdc = pd + cc * 1360;
#pragma unroll
            for (int k = 0; k < 9; k++) {
                int dy = k / 3, dx = k % 3;
                float a0 = pdc[(ty + dy) * 40 + tx + dx + 3];
                float a1 = pdc[(ty + dy) * 40 + tx + 16 + dx + 3];
                float a2 = pdc[(ty + 16 + dy) * 40 + tx + dx + 3];
                float a3 = pdc[(ty + 16 + dy) * 40 + tx + 16 + dx + 3];
                ull p0 = pk2(a0, a0), p1 = pk2(a1, a1);
                ull p2 = pk2(a2, a2), p3 = pk2(a3, a3);
                const ull* wr = wp + (cc * 9 + k) * 8;
#pragma unroll
                for (int j = 0; j < 8; j++) {
                    ull wv = wr[j];
                    acc2[j * 4 + 0] = ffma2(wv, p0, acc2[j * 4 + 0]);
                    acc2[j * 4 + 1] = ffma2(wv, p1, acc2[j * 4 + 1]);
                    acc2[j * 4 + 2] = ffma2(wv, p2, acc2[j * 4 + 2]);
                    acc2[j * 4 + 3] = ffma2(wv, p3, acc2[j * 4 + 3]);
                }
            }
        }
        __syncthreads();   // all warps done with buf before it is re-filled
    }

    // BN + ReLU epilogue, NHWC stores
    float sc[16], tc[16];
#pragma unroll
    for (int co = 0; co < 16; co++) {
        int c = co0 + co;
        sc[co] = gg[c] * rsqrtf(vvp[c] + 1e-5f);
        tc[co] = bbp[c] - mmp[c] * sc[co];
    }
#pragma unroll
    for (int q = 0; q < 4; q++) {
        int py = y0 + ty + ((q & 2) << 3);
        int px = x0 + tx + ((q & 1) << 4);
        float* dst = g_xmerge + ((size_t)b * HW + py * WW + px) * 256
                   + chan_base + co0;
        float v[16];
#pragma unroll
        for (int j = 0; j < 8; j++) {
            float lo, hi2;
            int qq = ((q & 2) ? 2 : 0) + (q & 1);
            upk2(acc2[j * 4 + qq], lo, hi2);
            v[j]     = fmaxf(lo  * sc[j]     + tc[j],     0.f);
            v[j + 8] = fmaxf(hi2 * sc[j + 8] + tc[j + 8], 0.f);
        }
#pragma unroll
        for (int c4 = 0; c4 < 4; c4++)
            ((float4*)dst)[c4] =
                make_float4(v[c4*4], v[c4*4+1], v[c4*4+2], v[c4*4+3]);
    }
}

// ---------------- 3) 1x1 convs: offset (18) + mask (9, sigmoid) --------------
__global__ void __launch_bounds__(256) offmask_kernel(
    const float* __restrict__ w_off, const float* __restrict__ b_off,
    const float* __restrict__ w_mask, const float* __restrict__ b_mask)
{
    __shared__ ull wpk[128 * 27];   // [j = c/2][o]
    int tid = threadIdx.x;
    for (int i = tid; i < 128 * 27; i += 256) {
        int j = i / 27, o = i % 27;
        int c = 2 * j;
        float lo = (o < 18) ? w_off[o * 256 + c]     : w_mask[(o - 18) * 256 + c];
        float hi = (o < 18) ? w_off[o * 256 + c + 1] : w_mask[(o - 18) * 256 + c + 1];
        wpk[i] = pk2(lo, hi);
    }
    __syncthreads();

    int gpix = blockIdx.x * 256 + tid;
    int b = gpix >> 14, pix = gpix & 16383;
    const ull* xp = (const ull*)(g_xmerge + (size_t)gpix * 256);

    ull acc2[27];
#pragma unroll
    for (int o = 0; o < 27; o++) acc2[o] = 0ull;

#pragma unroll 8
    for (int j = 0; j < 128; j++) {
        ull xv = __ldg(xp + j);
#pragma unroll
        for (int o = 0; o < 27; o++)
            acc2[o] = ffma2(wpk[j * 27 + o], xv, acc2[o]);
    }

#pragma unroll
    for (int o = 0; o < 18; o++) {
        float lo, hi; upk2(acc2[o], lo, hi);
        g_offset[((size_t)b * 18 + o) * HW + pix] = lo + hi + b_off[o];
    }
#pragma unroll
    for (int o = 0; o < 9; o++) {
        float lo, hi; upk2(acc2[18 + o], lo, hi);
        float a = lo + hi + b_mask[o];
        g_mask[((size_t)b * 9 + o) * HW + pix] = 1.f / (1.f + __expf(-a));
    }
}

// ---------------- 4) deformable conv 3x3 + ReLU ------------------------------
// block: 8x8 px tile x ALL 128 co; thread = 4 px x 8 co. (round-4, unchanged)
#define DEF_SMEM_BYTES 64512
__global__ void __launch_bounds__(256) deform_kernel(float* __restrict__ out)
{
    extern __shared__ __align__(16) char dyn[];
    ull*   wsk  = (ull*)dyn;
    float* vals = (float*)(dyn + 36864);
    int*   mI0  = (int*)(dyn + 46080);
    int*   mI1  = mI0 + 576;
    int*   mI2  = mI1 + 576;
    int*   mI3  = mI2 + 576;
    float* mW0  = (float*)(dyn + 55296);
    float* mW1  = mW0 + 576;
    float* mW2  = mW1 + 576;
    float* mW3  = mW2 + 576;

    int b = blockIdx.z;
    int gx0 = blockIdx.x << 3, gy0 = blockIdx.y << 3;
    int tid = threadIdx.x;

    for (int e = tid; e < 576; e += 256) {
        int p = e & 63, k = e >> 6;
        int gy = gy0 + (p >> 3), gx = gx0 + (p & 7);
        int pix = gy * WW + gx;
        float dy = g_offset[((size_t)b * 18 + 2 * k) * HW + pix];
        float dx = g_offset[((size_t)b * 18 + 2 * k + 1) * HW + pix];
        float mk = g_mask[((size_t)b * 9 + k) * HW + pix];
        float ys = (float)gy + (float)(k / 3 - 1) + dy;
        float xs = (float)gx + (float)(k % 3 - 1) + dx;
        float y0f = floorf(ys), x0f = floorf(xs);
        int y0 = (int)y0f, x0 = (int)x0f;
        float wy = ys - y0f, wx = xs - x0f;
        bool vy0 = (y0 >= 0) && (y0 < HH);
        bool vy1 = (y0 + 1 >= 0) && (y0 + 1 < HH);
        bool vx0 = (x0 >= 0) && (x0 < WW);
        bool vx1 = (x0 + 1 >= 0) && (x0 + 1 < WW);
        int y0c = min(max(y0, 0), HH - 1), y1c = min(max(y0 + 1, 0), HH - 1);
        int x0c = min(max(x0, 0), WW - 1), x1c = min(max(x0 + 1, 0), WW - 1);
        mI0[e] = (y0c * WW + x0c) * 256;  mW0[e] = (vy0 && vx0) ? (1.f - wy) * (1.f - wx) * mk : 0.f;
        mI1[e] = (y0c * WW + x1c) * 256;  mW1[e] = (vy0 && vx1) ? (1.f - wy) * wx * mk : 0.f;
        mI2[e] = (y1c * WW + x0c) * 256;  mW2[e] = (vy1 && vx0) ? wy * (1.f - wx) * mk : 0.f;
        mI3[e] = (y1c * WW + x1c) * 256;  mW3[e] = (vy1 && vx1) ? wy * wx * mk : 0.f;
    }

    ull acc2[16];                 // [j (8 co)][pr (2 px-pairs)]
#pragma unroll
    for (int i = 0; i < 16; i++) acc2[i] = 0ull;

    const float* xb = g_xmerge + (size_t)b * HW * 256;
    int ppg = tid & 15;
    int cog = tid >> 4;

    for (int q = 0; q < 64; q++) {
        int c0 = q * 4;
        __syncthreads();
        for (int e = tid; e < 576; e += 256) {
            int i0 = mI0[e], i1 = mI1[e], i2 = mI2[e], i3 = mI3[e];
            float w0 = mW0[e], w1 = mW1[e], w2 = mW2[e], w3 = mW3[e];
            float4 v0 = __ldg((const float4*)(xb + i0 + c0));
            float4 v1 = __ldg((const float4*)(xb + i1 + c0));
            float4 v2 = __ldg((const float4*)(xb + i2 + c0));
            float4 v3 = __ldg((const float4*)(xb + i3 + c0));
            int base = (e >> 6) * 64 + (e & 63);
            vals[base]        = w0*v0.x + w1*v1.x + w2*v2.x + w3*v3.x;
            vals[base + 576]  = w0*v0.y + w1*v1.y + w2*v2.y + w3*v3.y;
            vals[base + 1152] = w0*v0.z + w1*v1.z + w2*v2.z + w3*v3.z;
            vals[base + 1728] = w0*v0.w + w1*v1.w + w2*v2.w + w3*v3.w;
        }
        {
            const ulonglong2* src =
                (const ulonglong2*)(g_wtd + (size_t)q * 4608);
            ulonglong2* dst = (ulonglong2*)wsk;
            for (int i = tid; i < 2304; i += 256)
                dst[i] = __ldg(src + i);
        }
        __syncthreads();
#pragma unroll 6
        for (int ck = 0; ck < 36; ck++) {
            ull v0 = *(const ull*)&vals[ck * 64 + ppg * 4];
            ull v1 = *(const ull*)&vals[ck * 64 + ppg * 4 + 2];
            const ull* wr = wsk + ck * 128 + cog * 8;
#pragma unroll
            for (int j = 0; j < 8; j++) {
                ull wv = wr[j];
                acc2[j * 2 + 0] = ffma2(wv, v0, acc2[j * 2 + 0]);
                acc2[j * 2 + 1] = ffma2(wv, v1, acc2[j * 2 + 1]);
            }
        }
    }

#pragma unroll
    for (int j = 0; j < 8; j++) {
        int co = cog * 8 + j;
#pragma unroll
        for (int pr = 0; pr < 2; pr++) {
            float a0, a1; upk2(acc2[j * 2 + pr], a0, a1);
            int p = ppg * 4 + pr * 2;
            int gy = gy0 + (p >> 3), gx = gx0 + (p & 7);
            *(float2*)&out[((size_t)b * 128 + co) * HW + gy * WW + gx] =
                make_float2(fmaxf(a0, 0.f), fmaxf(a1, 0.f));
        }
    }
}

// ---------------- launch -----------------------------------------------------
extern "C" void kernel_launch(void* const* d_in, const int* in_sizes, int n_in,
                              void* d_out, int out_size) {
    const float* x_low  = (const float*)d_in[0];
    const float* x_high = (const float*)d_in[1];
    const float* w_low  = (const float*)d_in[2];
    const float* g_low  = (const float*)d_in[3];
    const float* b_low  = (const float*)d_in[4];
    const float* m_low  = (const float*)d_in[5];
    const float* v_low  = (const float*)d_in[6];
    const float* w_high = (const float*)d_in[7];
    const float* g_high = (const float*)d_in[8];
    const float* b_high = (const float*)d_in[9];
    const float* m_high = (const float*)d_in[10];
    const float* v_high = (const float*)d_in[11];
    const float* w_off  = (const float*)d_in[12];
    const float* b_off  = (const float*)d_in[13];
    const float* w_mask = (const float*)d_in[14];
    const float* b_mask = (const float*)d_in[15];
    const float* w_conv = (const float*)d_in[16];
    float* out = (float*)d_out;

    // opt-in >48KB dynamic smem (host-side immediate calls; capture-safe)
    cudaFuncSetAttribute(deform_kernel,
                         cudaFuncAttributeMaxDynamicSharedMemorySize,
                         DEF_SMEM_BYTES);
    cudaFuncSetAttribute(conv_fused,
                         cudaFuncAttributeMaxDynamicSharedMemorySize,
                         CONV_SMEM_BYTES);

    ull* wplow_ptr = nullptr; ull* wphigh_ptr = nullptr;
    cudaGetSymbolAddress((void**)&wplow_ptr, g_wplow);
    cudaGetSymbolAddress((void**)&wphigh_ptr, g_wphigh);

    pad_low_kernel<<<(NB * 128 * PADHW) / 256, 256>>>(x_low);
    upsample_pad_kernel<<<(NB * 256 * PADHW) / 256, 256>>>(x_high);
    wt_kernel<<<(64 * 36 * 128) / 256, 256>>>(w_conv);
    wpack_kernel<<<(8 * 32 * 288) / 256, 256>>>(w_low, wplow_ptr, 128);
    wpack_kernel<<<(8 * 64 * 288) / 256, 256>>>(w_high, wphigh_ptr, 256);

    conv_fused<<<dim3(4, 4, 32), dim3(16, 16), CONV_SMEM_BYTES>>>(
        g_low, b_low, m_low, v_low, g_high, b_high, m_high, v_high);

    offmask_kernel<<<128, 256>>>(w_off, b_off, w_mask, b_mask);

    deform_kernel<<<dim3(16, 16, NB), 256, DEF_SMEM_BYTES>>>(out);
}